// round 12
// baseline (speedup 1.0000x reference)
#include <cuda_runtime.h>
#include <float.h>
#include <math.h>
#include <stdint.h>

#define BB 8
#define LL 2048
#define DIN 256
#define DATT 128

// pair-zipped scratch: within each 8-float k-group, element w stored at
// zp8(w) = (w<4) ? 2w : 2(w-4)+1, so the mma fragment pair (k+t, k+t+4)
// is contiguous and loads with one LDS.64.
__device__ __align__(128) float g_inp[BB * LL * DATT];  // elu(ctx@W_in), zipped
__device__ __align__(128) float g_mem[BB * LL * DATT];  // elu(qry@W_mem), zipped
__device__ __align__(128) float g_vt [BB * DIN * LL];   // V^T, tf32, q-zipped

__device__ __host__ __forceinline__ int zp8(int w) {
    return (w < 4) ? 2 * w : 2 * (w - 4) + 1;
}
__device__ __host__ __forceinline__ int ZQ(int k) {
    return (k & ~7) | zp8(k & 7);
}

__device__ __forceinline__ float elu01(float v) {
    return v > 0.0f ? v : 0.01f * expm1f(v);
}
__device__ __forceinline__ float f2tf(float v) {
    uint32_t r;
    asm("cvt.rna.tf32.f32 %0, %1;" : "=r"(r) : "f"(v));
    return __uint_as_float(r);
}
__device__ __forceinline__ float fex2(float x) {
    float r;
    asm("ex2.approx.f32 %0, %1;" : "=f"(r) : "f"(x));
    return r;
}
__device__ __forceinline__ uint32_t fu(float v) { return __float_as_uint(v); }

__device__ __forceinline__ void mma8(float d[4],
                                     uint32_t a0, uint32_t a1, uint32_t a2, uint32_t a3,
                                     uint32_t b0, uint32_t b1) {
    asm volatile(
        "mma.sync.aligned.m16n8k8.row.col.f32.tf32.tf32.f32 "
        "{%0,%1,%2,%3},{%4,%5,%6,%7},{%8,%9},{%0,%1,%2,%3};\n"
        : "+f"(d[0]), "+f"(d[1]), "+f"(d[2]), "+f"(d[3])
        : "r"(a0), "r"(a1), "r"(a2), "r"(a3), "r"(b0), "r"(b1));
}

__device__ __forceinline__ void cpa16(uint32_t dst, const float* src) {
    asm volatile("cp.async.cg.shared.global [%0], [%1], 16;\n" :: "r"(dst), "l"(src));
}
#define CPA_COMMIT() asm volatile("cp.async.commit_group;\n" ::: "memory")
#define CPA_WAIT0()  asm volatile("cp.async.wait_group 0;\n" ::: "memory")
#define CPA_WAIT1()  asm volatile("cp.async.wait_group 1;\n" ::: "memory")

// ---------------------------------------------------------------------------
// Kernel 0: vprep — transpose + tf32-round + q-zip V into g_vt[B][256][2048].
// ---------------------------------------------------------------------------
__global__ __launch_bounds__(256) void vprep_kernel(const float* __restrict__ qry)
{
    __shared__ float T[32][33];
    const int q0 = blockIdx.x * 32;
    const int d0 = blockIdx.y * 32;
    const int b  = blockIdx.z;
    const int tx = threadIdx.x, ty = threadIdx.y;

#pragma unroll
    for (int r = 0; r < 4; r++) {
        int q = q0 + ty * 4 + r;
        T[ty * 4 + r][tx] = qry[(size_t)(b * LL + q) * DIN + d0 + tx];
    }
    __syncthreads();
#pragma unroll
    for (int r = 0; r < 4; r++) {
        int d = d0 + ty * 4 + r;
        g_vt[(size_t)(b * DIN + d) * LL + ZQ(q0 + tx)] = f2tf(T[tx][ty * 4 + r]);
    }
}

// ---------------------------------------------------------------------------
// Kernel 1: projections on tensor cores, epilogue stores ZIPPED columns.
// ---------------------------------------------------------------------------
__global__ __launch_bounds__(256) void proj_kernel(
    const float* __restrict__ ctx, const float* __restrict__ qry,
    const float* __restrict__ Win, const float* __restrict__ Wmem)
{
    const int which = blockIdx.y;
    const float* X = (which == 0) ? ctx : qry;
    const float* W = (which == 0) ? Win : Wmem;
    float* O = (which == 0) ? g_inp : g_mem;

    __shared__ float Xs[128 * 36];
    __shared__ float Ws[32 * 136];

    const int tid  = threadIdx.x;
    const int w    = tid >> 5;
    const int lane = tid & 31;
    const int g = lane >> 2;
    const int t = lane & 3;
    const int r0 = (w >> 1) * 32;
    const int n0 = (w & 1) * 64;
    const int m0 = blockIdx.x * 128;

    float acc[2][8][4];
#pragma unroll
    for (int mi = 0; mi < 2; mi++)
#pragma unroll
        for (int j = 0; j < 8; j++)
#pragma unroll
            for (int r = 0; r < 4; r++) acc[mi][j][r] = 0.f;

    for (int kt = 0; kt < 8; kt++) {
#pragma unroll
        for (int i = 0; i < 4; i++) {
            int idx = tid + i * 256;
            int row = idx >> 3, c4 = idx & 7;
            *reinterpret_cast<float4*>(&Xs[row * 36 + c4 * 4]) =
                *reinterpret_cast<const float4*>(
                    &X[(size_t)(m0 + row) * DIN + kt * 32 + c4 * 4]);
        }
#pragma unroll
        for (int i = 0; i < 4; i++) {
            int idx = tid + i * 256;
            int row = idx >> 5, c = idx & 31;
            *reinterpret_cast<float4*>(&Ws[row * 136 + c * 4]) =
                *reinterpret_cast<const float4*>(
                    &W[(size_t)(kt * 32 + row) * DATT + c * 4]);
        }
        __syncthreads();

#pragma unroll
        for (int ks = 0; ks < 4; ks++) {
            int k0 = ks * 8;
            uint32_t a[2][4];
#pragma unroll
            for (int mi = 0; mi < 2; mi++) {
                int rr = r0 + 16 * mi + g;
                a[mi][0] = fu(Xs[rr * 36 + k0 + t]);
                a[mi][1] = fu(Xs[(rr + 8) * 36 + k0 + t]);
                a[mi][2] = fu(Xs[rr * 36 + k0 + t + 4]);
                a[mi][3] = fu(Xs[(rr + 8) * 36 + k0 + t + 4]);
            }
#pragma unroll
            for (int j = 0; j < 8; j++) {
                uint32_t b0 = fu(Ws[(k0 + t) * 136 + n0 + 8 * j + g]);
                uint32_t b1 = fu(Ws[(k0 + t + 4) * 136 + n0 + 8 * j + g]);
#pragma unroll
                for (int mi = 0; mi < 2; mi++)
                    mma8(acc[mi][j], a[mi][0], a[mi][1], a[mi][2], a[mi][3], b0, b1);
            }
        }
        __syncthreads();
    }

#pragma unroll
    for (int mi = 0; mi < 2; mi++) {
        float* O0 = O + (size_t)(m0 + r0 + 16 * mi + g) * DATT;
        float* O1 = O0 + (size_t)8 * DATT;
#pragma unroll
        for (int j = 0; j < 8; j++) {
            int cl = n0 + 8 * j + 2 * t;
            int z0 = ZQ(cl);
            O0[z0]     = f2tf(elu01(acc[mi][j][0]));
            O0[z0 + 2] = f2tf(elu01(acc[mi][j][1]));
            O1[z0]     = f2tf(elu01(acc[mi][j][2]));
            O1[z0 + 2] = f2tf(elu01(acc[mi][j][3]));
        }
    }
}

// ---------------------------------------------------------------------------
// Kernel 2: fused flash attention.  cp.async tiles, LDS.64 fragments,
// additive-bias masking, tile-level diagonal branch, zipped Ps.
// grid (16,8), block 512.
// ---------------------------------------------------------------------------
#define TQ 128
#define TK 64
#define QP2 136   // Qs/Ks pitch (mod 32 == 8)
#define VTP 72    // VT pitch    (mod 32 == 8)
#define PP  72    // Ps pitch    (mod 32 == 8 -> clean LDS.64 wavefronts)

#define OFF_Q   0
#define OFF_K   (OFF_Q + TQ * QP2)            // 17408
#define OFF_VT  (OFF_K + TK * QP2)            // 26112
#define OFF_P   (OFF_VT + DIN * VTP)          // 44544
#define OFF_L   (OFF_P + TQ * PP)             // 53760
#define OFF_B   (OFF_L + 2 * TQ)              // 54016  (float bias[TK])
#define SMEMF   (OFF_B + TK)                  // 54080 floats
#define SMEMB   (SMEMF * 4)                   // 216320 bytes

__global__ __launch_bounds__(512, 1) void attn_kernel(
    const int*   __restrict__ qmask,     // [B,L]
    float*       __restrict__ out)       // [B,L,256]
{
    extern __shared__ float sm[];
    float* Qs    = sm + OFF_Q;
    float* Ks    = sm + OFF_K;
    float* VT    = sm + OFF_VT;
    float* Ps    = sm + OFF_P;
    float* redL  = sm + OFF_L;
    float* biasS = sm + OFF_B;
    const uint32_t smb = (uint32_t)__cvta_generic_to_shared(sm);

    const int b   = blockIdx.y;
    const int c0  = blockIdx.x * TQ;
    const int tid = threadIdx.x;
    const int w    = tid >> 5;
    const int lane = tid & 31;
    const int g = lane >> 2;
    const int t = lane & 3;
    const int wr  = w >> 1, wc  = w & 1;    // GEMM1: 8 rowgrp x 2 colgrp
    const int wr2 = w >> 2, wc2 = w & 3;    // GEMM2: 4 rowgrp x 4 colgrp
    const int r0  = wr * 16;
    const int nq0 = wc * 32;
    const int r2  = wr2 * 32;
    const int n2  = wc2 * 64;
    const float cs = 0.12751743f;           // (1/sqrt(128)) * log2(e)

    // cp.async thread mappings
    const int qrow = tid >> 5, qch = tid & 31;   // Q/K: 32 16B-chunks per row
    const int vdv  = tid >> 4, vch = tid & 15;   // VT: 16 16B-chunks per dv-row

    // ---- prologue: Q + K(0) (group A), V(0) (group B), bias(0) ----
#pragma unroll
    for (int i = 0; i < 8; i++) {
        int row = qrow + i * 16;
        cpa16(smb + (uint32_t)(OFF_Q + row * QP2 + qch * 4) * 4u,
              &g_inp[(size_t)(b * LL + c0 + row) * DATT + qch * 4]);
    }
#pragma unroll
    for (int i = 0; i < 4; i++) {
        int row = qrow + i * 16;
        cpa16(smb + (uint32_t)(OFF_K + row * QP2 + qch * 4) * 4u,
              &g_mem[(size_t)(b * LL + row) * DATT + qch * 4]);
    }
    CPA_COMMIT();   // {Q, K0}
#pragma unroll
    for (int i = 0; i < 8; i++) {
        int dv = vdv + i * 32;
        cpa16(smb + (uint32_t)(OFF_VT + dv * VTP + vch * 4) * 4u,
              &g_vt[(size_t)(b * DIN + dv) * LL + vch * 4]);
    }
    CPA_COMMIT();   // {V0}
    if (tid < TK) biasS[tid] = (qmask[b * LL + tid] > 0) ? 0.f : -1e30f;

    float o[2][8][4];
#pragma unroll
    for (int mi = 0; mi < 2; mi++)
#pragma unroll
        for (int j = 0; j < 8; j++)
#pragma unroll
            for (int r = 0; r < 4; r++) o[mi][j][r] = 0.f;
    float lsum0 = 0.f, lsum1 = 0.f;

#pragma unroll 1
    for (int q0 = 0; q0 < LL; q0 += TK) {
        const int q0n = (q0 + TK < LL) ? (q0 + TK) : q0;

        CPA_WAIT1();       // K(i) (+Q) complete
        __syncthreads();   // sync_top: K(i)/bias(i) visible

        // ---- GEMM1: S[128,64] = Q.K^T (LDS.64 zipped fragments) ----
        float s[4][4];
#pragma unroll
        for (int j = 0; j < 4; j++)
#pragma unroll
            for (int r = 0; r < 4; r++) s[j][r] = 0.f;

        const int qa0 = (r0 + g) * QP2 + 2 * t;
        const int qa1 = (r0 + g + 8) * QP2 + 2 * t;
#pragma unroll
        for (int k0 = 0; k0 < DATT; k0 += 8) {
            float2 pa = *reinterpret_cast<const float2*>(&Qs[qa0 + k0]);  // (a0,a2)
            float2 pb = *reinterpret_cast<const float2*>(&Qs[qa1 + k0]);  // (a1,a3)
#pragma unroll
            for (int j = 0; j < 4; j++) {
                float2 kb = *reinterpret_cast<const float2*>(
                    &Ks[(nq0 + 8 * j + g) * QP2 + k0 + 2 * t]);           // (b0,b1)
                mma8(s[j], fu(pa.x), fu(pb.x), fu(pa.y), fu(pb.y), fu(kb.x), fu(kb.y));
            }
        }

        // mask(i+1) prefetch
        int mv = 0;
        if (tid < TK) mv = qmask[b * LL + q0n + tid];

        // ---- softmax: p = exp2(fma(s, cs, bias)); diagonal only in 2/32 tiles ----
        {
            const int cg0 = c0 + r0 + g, cg1 = cg0 + 8;
            const int pz0 = zp8(2 * t), pz1 = zp8(2 * t + 1);
            const bool has_diag = (q0 >= c0) && (q0 < c0 + TQ);
            float su0 = 0.f, su1 = 0.f;
#pragma unroll
            for (int j = 0; j < 4; j++) {
                int cl = nq0 + 8 * j + 2 * t;
                float2 bb = *reinterpret_cast<const float2*>(&biasS[cl]);
                float p00 = fex2(fmaf(s[j][0], cs, bb.x));
                float p01 = fex2(fmaf(s[j][1], cs, bb.y));
                float p10 = fex2(fmaf(s[j][2], cs, bb.x));
                float p11 = fex2(fmaf(s[j][3], cs, bb.y));
                if (has_diag) {
                    int qg0 = q0 + cl;
                    if (cg0 == qg0)     p00 = 0.f;
                    if (cg0 == qg0 + 1) p01 = 0.f;
                    if (cg1 == qg0)     p10 = 0.f;
                    if (cg1 == qg0 + 1) p11 = 0.f;
                }
                su0 += p00 + p01;
                su1 += p10 + p11;
                int base0 = (r0 + g) * PP + nq0 + 8 * j;
                int base1 = (r0 + g + 8) * PP + nq0 + 8 * j;
                Ps[base0 + pz0] = f2tf(p00);
                Ps[base0 + pz1] = f2tf(p01);
                Ps[base1 + pz0] = f2tf(p10);
                Ps[base1 + pz1] = f2tf(p11);
            }
            su0 += __shfl_xor_sync(0xffffffffu, su0, 1);
            su0 += __shfl_xor_sync(0xffffffffu, su0, 2);
            su1 += __shfl_xor_sync(0xffffffffu, su1, 1);
            su1 += __shfl_xor_sync(0xffffffffu, su1, 2);
            lsum0 += su0;
            lsum1 += su1;
        }

        CPA_WAIT0();       // V(i) complete
        __syncthreads();   // sync_C: Ps + V(i) visible; Ks free

        // issue K(i+1); store bias(i+1)
        if (q0n != q0) {
#pragma unroll
            for (int i = 0; i < 4; i++) {
                int row = qrow + i * 16;
                cpa16(smb + (uint32_t)(OFF_K + row * QP2 + qch * 4) * 4u,
                      &g_mem[(size_t)(b * LL + q0n + row) * DATT + qch * 4]);
            }
            CPA_COMMIT();
        }
        if (tid < TK) biasS[tid] = (mv > 0) ? 0.f : -1e30f;

        // ---- GEMM2: O[128,256] += P . V (zipped LDS.64 A and B frags) ----
        const int pa0base = (r2 + g) * PP + 2 * t;
        const int pa1base = (r2 + g + 8) * PP + 2 * t;
        const int pa2base = (r2 + 16 + g) * PP + 2 * t;
        const int pa3base = (r2 + 24 + g) * PP + 2 * t;
#pragma unroll
        for (int k0 = 0; k0 < TK; k0 += 8) {
            float2 a02_0 = *reinterpret_cast<const float2*>(&Ps[pa0base + k0]); // (a0,a2) mi=0
            float2 a13_0 = *reinterpret_cast<const float2*>(&Ps[pa1base + k0]); // (a1,a3) mi=0
            float2 a02_1 = *reinterpret_cast<const float2*>(&Ps[pa2base + k0]); // mi=1
            float2 a13_1 = *reinterpret_cast<const float2*>(&Ps[pa3base + k0]);
#pragma unroll
            for (int j = 0; j < 8; j++) {
                float2 vb = *reinterpret_cast<const float2*>(
                    &VT[(n2 + 8 * j + g) * VTP + k0 + 2 * t]);                  // (b0,b1)
                mma8(o[0][j], fu(a02_0.x), fu(a13_0.x), fu(a02_0.y), fu(a13_0.y),
                     fu(vb.x), fu(vb.y));
                mma8(o[1][j], fu(a02_1.x), fu(a13_1.x), fu(a02_1.y), fu(a13_1.y),
                     fu(vb.x), fu(vb.y));
            }
        }

        __syncthreads();   // sync_A: GEMM2 reads of VT(i) done

        // issue V(i+1)
        if (q0n != q0) {
#pragma unroll
            for (int i = 0; i < 8; i++) {
                int dv = vdv + i * 32;
                cpa16(smb + (uint32_t)(OFF_VT + dv * VTP + vch * 4) * 4u,
                      &g_vt[(size_t)(b * DIN + dv) * LL + q0n + vch * 4]);
            }
            CPA_COMMIT();
        }
    }

    CPA_WAIT0();
    // ---- row sums -> normalize + store ----
    if (t == 0) {
        redL[wc * TQ + r0 + g]     = lsum0;
        redL[wc * TQ + r0 + g + 8] = lsum1;
    }
    __syncthreads();

#pragma unroll
    for (int mi = 0; mi < 2; mi++) {
        int rr0 = r2 + 16 * mi + g;
        int rr1 = rr0 + 8;
        float l0 = 1.0f / (redL[rr0] + redL[TQ + rr0]);
        float l1 = 1.0f / (redL[rr1] + redL[TQ + rr1]);
        size_t rb0 = (size_t)(b * LL + c0 + rr0) * DIN;
        size_t rb1 = (size_t)(b * LL + c0 + rr1) * DIN;
#pragma unroll
        for (int j = 0; j < 8; j++) {
            int cl = n2 + 8 * j + 2 * t;
            *reinterpret_cast<float2*>(&out[rb0 + cl]) =
                make_float2(o[mi][j][0] * l0, o[mi][j][1] * l0);
            *reinterpret_cast<float2*>(&out[rb1 + cl]) =
                make_float2(o[mi][j][2] * l1, o[mi][j][3] * l1);
        }
    }
}

// ---------------------------------------------------------------------------
extern "C" void kernel_launch(void* const* d_in, const int* in_sizes, int n_in,
                              void* d_out, int out_size)
{
    const float* ctx  = (const float*)d_in[0];
    const float* qry  = (const float*)d_in[1];
    const float* Win  = (const float*)d_in[2];
    const float* Wmem = (const float*)d_in[3];
    const int*   msk  = (const int*)d_in[4];
    float* out = (float*)d_out;

    (void)in_sizes; (void)n_in; (void)out_size;

    cudaFuncSetAttribute(attn_kernel,
                         cudaFuncAttributeMaxDynamicSharedMemorySize, SMEMB);

    vprep_kernel<<<dim3(LL / 32, DIN / 32, BB), dim3(32, 8)>>>(qry);
    proj_kernel<<<dim3(BB * LL / 128, 2), 256>>>(ctx, qry, Win, Wmem);
    attn_kernel<<<dim3(LL / TQ, BB), 512, SMEMB>>>(msk, out);
}

// round 17
// speedup vs baseline: 1.0586x; 1.0586x over previous
#include <cuda_runtime.h>
#include <float.h>
#include <math.h>
#include <stdint.h>

#define BB 8
#define LL 2048
#define DIN 256
#define DATT 128

// pair-zipped scratch: within each 8-float k-group, element w stored at
// zp8(w) = (w<4) ? 2w : 2(w-4)+1, so the mma fragment pair (k+t, k+t+4)
// is contiguous and loads with one LDS.64.
__device__ __align__(128) float g_inp[BB * LL * DATT];  // elu(ctx@W_in), zipped
__device__ __align__(128) float g_mem[BB * LL * DATT];  // elu(qry@W_mem), zipped
__device__ __align__(128) float g_vt [BB * DIN * LL];   // V^T, tf32, q-zipped

__device__ __host__ __forceinline__ int zp8(int w) {
    return (w < 4) ? 2 * w : 2 * (w - 4) + 1;
}
__device__ __host__ __forceinline__ int ZQ(int k) {
    return (k & ~7) | zp8(k & 7);
}

__device__ __forceinline__ float elu01(float v) {
    return v > 0.0f ? v : 0.01f * expm1f(v);
}
__device__ __forceinline__ float f2tf(float v) {
    uint32_t r;
    asm("cvt.rna.tf32.f32 %0, %1;" : "=r"(r) : "f"(v));
    return __uint_as_float(r);
}
__device__ __forceinline__ float fex2(float x) {
    float r;
    asm("ex2.approx.f32 %0, %1;" : "=f"(r) : "f"(x));
    return r;
}
__device__ __forceinline__ uint32_t fu(float v) { return __float_as_uint(v); }

__device__ __forceinline__ void mma8(float d[4],
                                     uint32_t a0, uint32_t a1, uint32_t a2, uint32_t a3,
                                     uint32_t b0, uint32_t b1) {
    asm volatile(
        "mma.sync.aligned.m16n8k8.row.col.f32.tf32.tf32.f32 "
        "{%0,%1,%2,%3},{%4,%5,%6,%7},{%8,%9},{%0,%1,%2,%3};\n"
        : "+f"(d[0]), "+f"(d[1]), "+f"(d[2]), "+f"(d[3])
        : "r"(a0), "r"(a1), "r"(a2), "r"(a3), "r"(b0), "r"(b1));
}

__device__ __forceinline__ void cpa16(uint32_t dst, const float* src) {
    asm volatile("cp.async.cg.shared.global [%0], [%1], 16;\n" :: "r"(dst), "l"(src));
}
#define CPA_COMMIT() asm volatile("cp.async.commit_group;\n" ::: "memory")
#define CPA_WAIT0()  asm volatile("cp.async.wait_group 0;\n" ::: "memory")

// ---------------------------------------------------------------------------
// Kernel 1: fused prep.  Blocks [0,256): projections (tensor cores, zipped
// epilogue).  Blocks [256, 4352): V transpose + tf32 + q-zip into g_vt.
// Fusing overlaps the DRAM-bound vprep with the tensor-bound proj.
// ---------------------------------------------------------------------------
__global__ __launch_bounds__(256) void prep_kernel(
    const float* __restrict__ ctx, const float* __restrict__ qry,
    const float* __restrict__ Win, const float* __restrict__ Wmem)
{
    const int bx  = blockIdx.x;
    const int tid = threadIdx.x;

    if (bx >= 256) {
        // ---------------- vprep part ----------------
        __shared__ float T[32][33];
        const int v    = bx - 256;            // [0, 4096)
        const int q0   = (v & 63) * 32;
        const int d0   = ((v >> 6) & 7) * 32;
        const int b    = v >> 9;
        const int tx = tid & 31, ty = tid >> 5;

#pragma unroll
        for (int r = 0; r < 4; r++) {
            int q = q0 + ty * 4 + r;
            T[ty * 4 + r][tx] = qry[(size_t)(b * LL + q) * DIN + d0 + tx];
        }
        __syncthreads();
#pragma unroll
        for (int r = 0; r < 4; r++) {
            int d = d0 + ty * 4 + r;
            g_vt[(size_t)(b * DIN + d) * LL + ZQ(q0 + tx)] = f2tf(T[tx][ty * 4 + r]);
        }
        return;
    }

    // ---------------- proj part ----------------
    const int which = bx >> 7;
    const float* X = (which == 0) ? ctx : qry;
    const float* W = (which == 0) ? Win : Wmem;
    float* O = (which == 0) ? g_inp : g_mem;

    __shared__ float Xs[128 * 36];
    __shared__ float Ws[32 * 136];

    const int w    = tid >> 5;
    const int lane = tid & 31;
    const int g = lane >> 2;
    const int t = lane & 3;
    const int r0 = (w >> 1) * 32;
    const int n0 = (w & 1) * 64;
    const int m0 = (bx & 127) * 128;

    float acc[2][8][4];
#pragma unroll
    for (int mi = 0; mi < 2; mi++)
#pragma unroll
        for (int j = 0; j < 8; j++)
#pragma unroll
            for (int r = 0; r < 4; r++) acc[mi][j][r] = 0.f;

    for (int kt = 0; kt < 8; kt++) {
#pragma unroll
        for (int i = 0; i < 4; i++) {
            int idx = tid + i * 256;
            int row = idx >> 3, c4 = idx & 7;
            *reinterpret_cast<float4*>(&Xs[row * 36 + c4 * 4]) =
                *reinterpret_cast<const float4*>(
                    &X[(size_t)(m0 + row) * DIN + kt * 32 + c4 * 4]);
        }
#pragma unroll
        for (int i = 0; i < 4; i++) {
            int idx = tid + i * 256;
            int row = idx >> 5, c = idx & 31;
            *reinterpret_cast<float4*>(&Ws[row * 136 + c * 4]) =
                *reinterpret_cast<const float4*>(
                    &W[(size_t)(kt * 32 + row) * DATT + c * 4]);
        }
        __syncthreads();

#pragma unroll
        for (int ks = 0; ks < 4; ks++) {
            int k0 = ks * 8;
            uint32_t a[2][4];
#pragma unroll
            for (int mi = 0; mi < 2; mi++) {
                int rr = r0 + 16 * mi + g;
                a[mi][0] = fu(Xs[rr * 36 + k0 + t]);
                a[mi][1] = fu(Xs[(rr + 8) * 36 + k0 + t]);
                a[mi][2] = fu(Xs[rr * 36 + k0 + t + 4]);
                a[mi][3] = fu(Xs[(rr + 8) * 36 + k0 + t + 4]);
            }
#pragma unroll
            for (int j = 0; j < 8; j++) {
                uint32_t b0 = fu(Ws[(k0 + t) * 136 + n0 + 8 * j + g]);
                uint32_t b1 = fu(Ws[(k0 + t + 4) * 136 + n0 + 8 * j + g]);
#pragma unroll
                for (int mi = 0; mi < 2; mi++)
                    mma8(acc[mi][j], a[mi][0], a[mi][1], a[mi][2], a[mi][3], b0, b1);
            }
        }
        __syncthreads();
    }

#pragma unroll
    for (int mi = 0; mi < 2; mi++) {
        float* O0 = O + (size_t)(m0 + r0 + 16 * mi + g) * DATT;
        float* O1 = O0 + (size_t)8 * DATT;
#pragma unroll
        for (int j = 0; j < 8; j++) {
            int cl = n0 + 8 * j + 2 * t;
            int z0 = ZQ(cl);
            O0[z0]     = f2tf(elu01(acc[mi][j][0]));
            O0[z0 + 2] = f2tf(elu01(acc[mi][j][1]));
            O1[z0]     = f2tf(elu01(acc[mi][j][2]));
            O1[z0 + 2] = f2tf(elu01(acc[mi][j][3]));
        }
    }
}

// ---------------------------------------------------------------------------
// Kernel 2: fused flash attention — R10 champion arithmetic/layout with a
// 2-barrier pipeline:
//   [issue V(i)] GEMM1 softmax+Pstore waitV syncF [issue K(i+1), mask(i+1)]
//   GEMM2 waitK syncJ
// grid (16,8), block 512.
// ---------------------------------------------------------------------------
#define TQ 128
#define TK 64
#define QP2 136   // Qs/Ks pitch (mod 32 == 8)
#define VTP 72    // VT pitch    (mod 32 == 8)
#define PP 68     // Ps pitch (plain layout)

#define OFF_Q   0
#define OFF_K   (OFF_Q + TQ * QP2)            // 17408
#define OFF_VT  (OFF_K + TK * QP2)            // 26112
#define OFF_P   (OFF_VT + DIN * VTP)          // 44544
#define OFF_L   (OFF_P + TQ * PP)             // 53248
#define OFF_MSK (OFF_L + 2 * TQ)              // 53504
#define SMEMF   (OFF_MSK + TK)                // 53568 floats
#define SMEMB   (SMEMF * 4)                   // 214272 bytes

__global__ __launch_bounds__(512, 1) void attn_kernel(
    const int*   __restrict__ qmask,     // [B,L]
    float*       __restrict__ out)       // [B,L,256]
{
    extern __shared__ float sm[];
    float* Qs   = sm + OFF_Q;
    float* Ks   = sm + OFF_K;
    float* VT   = sm + OFF_VT;
    float* Ps   = sm + OFF_P;
    float* redL = sm + OFF_L;
    int*   vmsk = reinterpret_cast<int*>(sm + OFF_MSK);
    const uint32_t smb = (uint32_t)__cvta_generic_to_shared(sm);

    const int b   = blockIdx.y;
    const int c0  = blockIdx.x * TQ;
    const int tid = threadIdx.x;
    const int w    = tid >> 5;
    const int lane = tid & 31;
    const int g = lane >> 2;
    const int t = lane & 3;
    const int wr  = w >> 1, wc  = w & 1;    // GEMM1: 8 rowgrp x 2 colgrp
    const int wr2 = w >> 2, wc2 = w & 3;    // GEMM2: 4 rowgrp x 4 colgrp
    const int r0  = wr * 16;
    const int nq0 = wc * 32;
    const int r2  = wr2 * 32;
    const int n2  = wc2 * 64;
    const float cs = 0.12751743f;           // (1/sqrt(128)) * log2(e)

    // cp.async thread mappings
    const int qrow = tid >> 5, qch = tid & 31;   // Q/K: 32 16B-chunks per row
    const int vdv  = tid >> 4, vch = tid & 15;   // VT: 16 16B-chunks per dv-row

    // ---- prologue: Q + K(0) cp.async, mask(0) ----
#pragma unroll
    for (int i = 0; i < 8; i++) {
        int row = qrow + i * 16;
        cpa16(smb + (uint32_t)(OFF_Q + row * QP2 + qch * 4) * 4u,
              &g_inp[(size_t)(b * LL + c0 + row) * DATT + qch * 4]);
    }
#pragma unroll
    for (int i = 0; i < 4; i++) {
        int row = qrow + i * 16;
        cpa16(smb + (uint32_t)(OFF_K + row * QP2 + qch * 4) * 4u,
              &g_mem[(size_t)(b * LL + row) * DATT + qch * 4]);
    }
    CPA_COMMIT();
    if (tid < TK) vmsk[tid] = qmask[b * LL + tid];

    float o[2][8][4];
#pragma unroll
    for (int mi = 0; mi < 2; mi++)
#pragma unroll
        for (int j = 0; j < 8; j++)
#pragma unroll
            for (int r = 0; r < 4; r++) o[mi][j][r] = 0.f;
    float lsum0 = 0.f, lsum1 = 0.f;

    CPA_WAIT0();
    __syncthreads();   // Q/K(0)/mask(0) visible

#pragma unroll 1
    for (int q0 = 0; q0 < LL; q0 += TK) {
        const int q0n = (q0 + TK < LL) ? (q0 + TK) : q0;

        // ---- A: issue V(i) into VT (free: GEMM2(i-1) ended before syncJ) ----
#pragma unroll
        for (int i = 0; i < 8; i++) {
            int dv = vdv + i * 32;
            cpa16(smb + (uint32_t)(OFF_VT + dv * VTP + vch * 4) * 4u,
                  &g_vt[(size_t)(b * DIN + dv) * LL + q0 + vch * 4]);
        }
        CPA_COMMIT();

        // ---- B: GEMM1: S[128,64] = Q.K^T (LDS.64 zipped fragments) ----
        float s[4][4];
#pragma unroll
        for (int j = 0; j < 4; j++)
#pragma unroll
            for (int r = 0; r < 4; r++) s[j][r] = 0.f;

        const int qa0 = (r0 + g) * QP2 + 2 * t;
        const int qa1 = (r0 + g + 8) * QP2 + 2 * t;
#pragma unroll
        for (int k0 = 0; k0 < DATT; k0 += 8) {
            float2 pa = *reinterpret_cast<const float2*>(&Qs[qa0 + k0]);  // (a0,a2)
            float2 pb = *reinterpret_cast<const float2*>(&Qs[qa1 + k0]);  // (a1,a3)
#pragma unroll
            for (int j = 0; j < 4; j++) {
                float2 kb = *reinterpret_cast<const float2*>(
                    &Ks[(nq0 + 8 * j + g) * QP2 + k0 + 2 * t]);           // (b0,b1)
                mma8(s[j], fu(pa.x), fu(pb.x), fu(pa.y), fu(pb.y), fu(kb.x), fu(kb.y));
            }
        }

        // mask(i+1) prefetch
        int mv = 0;
        if (tid < TK) mv = qmask[b * LL + q0n + tid];

        // ---- C: fixed-max softmax + P store (Ps free since syncJ(i-1)) ----
        {
            const int cg0 = c0 + r0 + g, cg1 = cg0 + 8;
            float su0 = 0.f, su1 = 0.f;
#pragma unroll
            for (int j = 0; j < 4; j++) {
                int cl = nq0 + 8 * j + 2 * t;
                bool v0 = vmsk[cl] > 0, v1 = vmsk[cl + 1] > 0;
                int qg0 = q0 + cl, qg1 = qg0 + 1;
                float p00 = (v0 && cg0 != qg0) ? fex2(s[j][0] * cs) : 0.f;
                float p01 = (v1 && cg0 != qg1) ? fex2(s[j][1] * cs) : 0.f;
                float p10 = (v0 && cg1 != qg0) ? fex2(s[j][2] * cs) : 0.f;
                float p11 = (v1 && cg1 != qg1) ? fex2(s[j][3] * cs) : 0.f;
                su0 += p00 + p01;
                su1 += p10 + p11;
                *reinterpret_cast<float2*>(&Ps[(r0 + g) * PP + cl]) =
                    make_float2(f2tf(p00), f2tf(p01));
                *reinterpret_cast<float2*>(&Ps[(r0 + g + 8) * PP + cl]) =
                    make_float2(f2tf(p10), f2tf(p11));
            }
            su0 += __shfl_xor_sync(0xffffffffu, su0, 1);
            su0 += __shfl_xor_sync(0xffffffffu, su0, 2);
            su1 += __shfl_xor_sync(0xffffffffu, su1, 1);
            su1 += __shfl_xor_sync(0xffffffffu, su1, 2);
            lsum0 += su0;
            lsum1 += su1;
        }

        CPA_WAIT0();       // D: V(i) landed (only outstanding group)
        __syncthreads();   // F: publishes V(i)+P(i); GEMM1/softmax done -> Ks,vmsk free

        // ---- G: issue K(i+1); publish mask(i+1) ----
        if (q0n != q0) {
#pragma unroll
            for (int i = 0; i < 4; i++) {
                int row = qrow + i * 16;
                cpa16(smb + (uint32_t)(OFF_K + row * QP2 + qch * 4) * 4u,
                      &g_mem[(size_t)(b * LL + q0n + row) * DATT + qch * 4]);
            }
            CPA_COMMIT();
        }
        if (tid < TK) vmsk[tid] = mv;

        // ---- H: GEMM2: O[128,256] += P . V (VT LDS.64 B-fragments) ----
#pragma unroll
        for (int k0 = 0; k0 < TK; k0 += 8) {
            uint32_t a[2][4];
#pragma unroll
            for (int mi = 0; mi < 2; mi++) {
                int rr = r2 + 16 * mi + g;
                a[mi][0] = fu(Ps[rr * PP + k0 + t]);
                a[mi][1] = fu(Ps[(rr + 8) * PP + k0 + t]);
                a[mi][2] = fu(Ps[rr * PP + k0 + t + 4]);
                a[mi][3] = fu(Ps[(rr + 8) * PP + k0 + t + 4]);
            }
#pragma unroll
            for (int j = 0; j < 8; j++) {
                float2 vb = *reinterpret_cast<const float2*>(
                    &VT[(n2 + 8 * j + g) * VTP + k0 + 2 * t]);            // (b0,b1)
#pragma unroll
                for (int mi = 0; mi < 2; mi++)
                    mma8(o[mi][j], a[mi][0], a[mi][1], a[mi][2], a[mi][3],
                         fu(vb.x), fu(vb.y));
            }
        }

        CPA_WAIT0();       // I: K(i+1) landed (no-op on last iter)
        __syncthreads();   // J: publishes K(i+1)+mask(i+1); Ps/VT freed
    }

    // ---- per-colgroup row sums -> normalize + store ----
    if (t == 0) {
        redL[wc * TQ + r0 + g]     = lsum0;
        redL[wc * TQ + r0 + g + 8] = lsum1;
    }
    __syncthreads();

#pragma unroll
    for (int mi = 0; mi < 2; mi++) {
        int rr0 = r2 + 16 * mi + g;
        int rr1 = rr0 + 8;
        float l0 = 1.0f / (redL[rr0] + redL[TQ + rr0]);
        float l1 = 1.0f / (redL[rr1] + redL[TQ + rr1]);
        size_t rb0 = (size_t)(b * LL + c0 + rr0) * DIN;
        size_t rb1 = (size_t)(b * LL + c0 + rr1) * DIN;
#pragma unroll
        for (int j = 0; j < 8; j++) {
            int cl = n2 + 8 * j + 2 * t;
            *reinterpret_cast<float2*>(&out[rb0 + cl]) =
                make_float2(o[mi][j][0] * l0, o[mi][j][1] * l0);
            *reinterpret_cast<float2*>(&out[rb1 + cl]) =
                make_float2(o[mi][j][2] * l1, o[mi][j][3] * l1);
        }
    }
}

// ---------------------------------------------------------------------------
extern "C" void kernel_launch(void* const* d_in, const int* in_sizes, int n_in,
                              void* d_out, int out_size)
{
    const float* ctx  = (const float*)d_in[0];
    const float* qry  = (const float*)d_in[1];
    const float* Win  = (const float*)d_in[2];
    const float* Wmem = (const float*)d_in[3];
    const int*   msk  = (const int*)d_in[4];
    float* out = (float*)d_out;

    (void)in_sizes; (void)n_in; (void)out_size;

    cudaFuncSetAttribute(attn_kernel,
                         cudaFuncAttributeMaxDynamicSharedMemorySize, SMEMB);

    prep_kernel<<<256 + 4096, 256>>>(ctx, qry, Win, Wmem);
    attn_kernel<<<dim3(LL / TQ, BB), 512, SMEMB>>>(msk, out);
}